// round 9
// baseline (speedup 1.0000x reference)
#include <cuda_runtime.h>
#include <cstdint>

// SSIM loss, NCHW (32,3,512,512) fp32, 3x3 box, reflect pad 1, scalar mean.
// R8: R5 structure (best known) with (a) even/odd column deinterleaving so the
// horizontal 3-sum shares t=ve+vo between even/odd pixels (-1 add2, -~4 MOVs
// per quantity per row), (b) reflection peeled out of interior blocks (pure
// strength-reduced addressing), (c) no L2 prefetch (R7 regression), dual
// packed accumulators, 4-buffer distance-2 pipelined row ring.

#define H 512
#define W 512
#define PLANES (32 * 3)
#define RPB 32
#define BLOCKS_X (H / RPB)           // 16
#define NBLOCKS (BLOCKS_X * PLANES)  // 1536

typedef unsigned long long u64;

__device__ float g_partials[NBLOCKS];
__device__ unsigned int g_count = 0;

__device__ __forceinline__ u64 pk(float lo, float hi) {
    u64 r; asm("mov.b64 %0, {%1, %2};" : "=l"(r) : "f"(lo), "f"(hi)); return r;
}
__device__ __forceinline__ void unpk(u64 v, float& lo, float& hi) {
    asm("mov.b64 {%0, %1}, %2;" : "=f"(lo), "=f"(hi) : "l"(v));
}
__device__ __forceinline__ float lo64(u64 v) {
    float f; asm("{\n\t.reg .f32 t;\n\tmov.b64 {%0, t}, %1;\n\t}" : "=f"(f) : "l"(v)); return f;
}
__device__ __forceinline__ float hi64(u64 v) {
    float f; asm("{\n\t.reg .f32 t;\n\tmov.b64 {t, %0}, %1;\n\t}" : "=f"(f) : "l"(v)); return f;
}
__device__ __forceinline__ u64 add2(u64 a, u64 b) {
    u64 d; asm("add.rn.f32x2 %0, %1, %2;" : "=l"(d) : "l"(a), "l"(b)); return d;
}
__device__ __forceinline__ u64 sub2(u64 a, u64 b) {
    u64 d; asm("sub.rn.f32x2 %0, %1, %2;" : "=l"(d) : "l"(a), "l"(b)); return d;
}
__device__ __forceinline__ u64 mul2(u64 a, u64 b) {
    u64 d; asm("mul.rn.f32x2 %0, %1, %2;" : "=l"(d) : "l"(a), "l"(b)); return d;
}
__device__ __forceinline__ u64 fma2(u64 a, u64 b, u64 c) {
    u64 d; asm("fma.rn.f32x2 %0, %1, %2, %3;" : "=l"(d) : "l"(a), "l"(b), "l"(c)); return d;
}
__device__ __forceinline__ float rcpf(float x) {
    float r; asm("rcp.approx.ftz.f32 %0, %1;" : "=f"(r) : "f"(x)); return r;
}

__device__ __forceinline__ int refl(int i) {
    if (i < 0) return -i;
    if (i > H - 1) return 2 * (H - 1) - i;
    return i;
}

// Deinterleaved row: X0=(x0,x2), X1=(x1,x3) etc. + halo scalars (lanes 0/31).
struct RowR { u64 X0, X1, Y0, Y1; float hX, hY; };

struct K { u64 twop, n2p, p18, p9, c1p, c2p, nhp, php; };

__device__ __forceinline__ void load_row(RowR& R,
                                         const float* __restrict__ xp,
                                         const float* __restrict__ yp,
                                         int rr, int base, int hcol, bool doHalo) {
    const float4 xv = *reinterpret_cast<const float4*>(xp + rr * W + base);
    const float4 yv = *reinterpret_cast<const float4*>(yp + rr * W + base);
    R.X0 = pk(xv.x, xv.z); R.X1 = pk(xv.y, xv.w);   // even/odd deinterleave
    R.Y0 = pk(yv.x, yv.z); R.Y1 = pk(yv.y, yv.w);
    if (doHalo) {
        R.hX = __ldg(xp + rr * W + hcol);
        R.hY = __ldg(yp + rr * W + hcol);
    }
}

// SSIM on raw 3x3 window sums (packed pixel pair); /9 factors cancel:
//   n/d = (2A+81C1)(18 Sxy - 2A + 81C2) / ((B+C+81C1)(9(Sxx+Syy)-B-C+81C2))
__device__ __forceinline__ u64 ssim2(u64 Sx, u64 Sy, u64 Sxx, u64 Syy, u64 Sxy,
                                     const K& k) {
    u64 A  = mul2(Sx, Sy);
    u64 B  = mul2(Sx, Sx);
    u64 C  = mul2(Sy, Sy);
    u64 n1 = fma2(A, k.twop, k.c1p);
    u64 t  = fma2(A, k.n2p,  k.c2p);
    u64 n2 = fma2(Sxy, k.p18, t);
    u64 n  = mul2(n1, n2);
    u64 BC = add2(B, C);
    u64 d1 = add2(BC, k.c1p);
    u64 u  = sub2(k.c2p, BC);
    u64 d2 = fma2(add2(Sxx, Syy), k.p9, u);
    u64 d  = mul2(d1, d2);
    float dd0, dd1; unpk(d, dd0, dd1);
    u64 rp = pk(rcpf(dd0), rcpf(dd1));
    u64 q  = mul2(n, rp);
    return fma2(q, k.nhp, k.php);
}

// Horizontal 3-sum, deinterleaved: ve=(c0,c2) vo=(c1,c3) vertical sums.
// t = ve+vo = (c0+c1, c2+c3); even windows (c-1+c0+c1, c1+c2+c3);
// odd windows (c0+c1+c2, c2+c3+c4).
#define HQ(q, ve, vo, hv)                                                     \
    float s0_##q = lo64(ve), s2_##q = hi64(ve);                               \
    float s1_##q = lo64(vo), s3_##q = hi64(vo);                               \
    float lf_##q = __shfl_up_sync(0xffffffffu, s3_##q, 1);                    \
    float rt_##q = __shfl_down_sync(0xffffffffu, s0_##q, 1);                  \
    if (lane == 0)  lf_##q = (wseg == 0) ? s1_##q : hv;                       \
    if (lane == 31) rt_##q = (wseg == 3) ? s2_##q : hv;                       \
    u64 t_##q  = add2(ve, vo);                                                \
    u64 hE_##q = add2(pk(lf_##q, s1_##q), t_##q);                             \
    u64 hO_##q = add2(t_##q, pk(s2_##q, rt_##q));

__device__ __forceinline__ void emit(const RowR& A, const RowR& B, const RowR& C,
                                     u64& acc, int lane, int wseg, const K& k) {
    // vertical 3-sums (deinterleaved halves); squares/products as FMA chains
    u64 vX0  = add2(add2(A.X0, B.X0), C.X0);
    u64 vX1  = add2(add2(A.X1, B.X1), C.X1);
    u64 vY0  = add2(add2(A.Y0, B.Y0), C.Y0);
    u64 vY1  = add2(add2(A.Y1, B.Y1), C.Y1);
    u64 vXX0 = fma2(A.X0, A.X0, fma2(B.X0, B.X0, mul2(C.X0, C.X0)));
    u64 vXX1 = fma2(A.X1, A.X1, fma2(B.X1, B.X1, mul2(C.X1, C.X1)));
    u64 vYY0 = fma2(A.Y0, A.Y0, fma2(B.Y0, B.Y0, mul2(C.Y0, C.Y0)));
    u64 vYY1 = fma2(A.Y1, A.Y1, fma2(B.Y1, B.Y1, mul2(C.Y1, C.Y1)));
    u64 vXY0 = fma2(A.X0, A.Y0, fma2(B.X0, B.Y0, mul2(C.X0, C.Y0)));
    u64 vXY1 = fma2(A.X1, A.Y1, fma2(B.X1, B.Y1, mul2(C.X1, C.Y1)));

    // halo vertical sums (meaningful on lanes 0/31 only)
    float hvX  = A.hX + B.hX + C.hX;
    float hvY  = A.hY + B.hY + C.hY;
    float hvXX = fmaf(A.hX, A.hX, fmaf(B.hX, B.hX, C.hX * C.hX));
    float hvYY = fmaf(A.hY, A.hY, fmaf(B.hY, B.hY, C.hY * C.hY));
    float hvXY = fmaf(A.hX, A.hY, fmaf(B.hX, B.hY, C.hX * C.hY));

    HQ(X,  vX0,  vX1,  hvX)
    HQ(Y,  vY0,  vY1,  hvY)
    HQ(XX, vXX0, vXX1, hvXX)
    HQ(YY, vYY0, vYY1, hvYY)
    HQ(XY, vXY0, vXY1, hvXY)
    // even pixels (cols 0,2) and odd pixels (cols 1,3) — order irrelevant for the mean
    acc = add2(acc, ssim2(hE_X, hE_Y, hE_XX, hE_YY, hE_XY, k));
    acc = add2(acc, ssim2(hO_X, hO_Y, hO_XX, hO_YY, hO_XY, k));
}

// EDGE=true: apply reflect() to row indices (blocks touching image borders).
// EDGE=false: raw indices, lets ptxas strength-reduce the unrolled addressing.
template<bool EDGE>
__device__ __forceinline__ void process(const float* __restrict__ xp,
                                        const float* __restrict__ yp,
                                        int r0, int base, int hcol, bool doHalo,
                                        int lane, int wseg, const K& k,
                                        u64& acc0, u64& acc1) {
    RowR b0, b1, b2, b3;
    load_row(b0, xp, yp, EDGE ? refl(r0 - 1) : (r0 - 1), base, hcol, doHalo);
    load_row(b1, xp, yp, r0,     base, hcol, doHalo);
    load_row(b2, xp, yp, r0 + 1, base, hcol, doHalo);

    #pragma unroll
    for (int j = 0; j < RPB; j += 4) {
        const int rr = r0 + j;
        load_row(b3, xp, yp, EDGE ? refl(rr + 2) : (rr + 2), base, hcol, doHalo);
        emit(b0, b1, b2, acc0, lane, wseg, k);                 // row rr
        load_row(b0, xp, yp, EDGE ? refl(rr + 3) : (rr + 3), base, hcol, doHalo);
        emit(b1, b2, b3, acc1, lane, wseg, k);                 // row rr+1
        load_row(b1, xp, yp, EDGE ? refl(rr + 4) : (rr + 4), base, hcol, doHalo);
        emit(b2, b3, b0, acc0, lane, wseg, k);                 // row rr+2
        load_row(b2, xp, yp, EDGE ? refl(rr + 5) : (rr + 5), base, hcol, doHalo);
        emit(b3, b0, b1, acc1, lane, wseg, k);                 // row rr+3
    }
}

__global__ __launch_bounds__(128)
void ssim_main(const float* __restrict__ x, const float* __restrict__ y,
               float* __restrict__ out) {
    const int tid   = threadIdx.x;
    const int lane  = tid & 31;
    const int wseg  = tid >> 5;                 // 0..3, 128-col segment
    const int plane = blockIdx.y;
    const int r0    = blockIdx.x * RPB;

    const int segbase = wseg * 128;
    const int base    = segbase + lane * 4;
    const float* __restrict__ xp = x + (size_t)plane * H * W;
    const float* __restrict__ yp = y + (size_t)plane * H * W;

    const int  hcol   = (lane == 0) ? ((wseg == 0) ? 1 : segbase - 1)
                                    : ((wseg == 3) ? 510 : segbase + 128);
    const bool doHalo = (lane == 0) || (lane == 31);

    K k;
    k.twop = pk(2.0f, 2.0f);
    k.n2p  = pk(-2.0f, -2.0f);
    k.p18  = pk(18.0f, 18.0f);
    k.p9   = pk(9.0f, 9.0f);
    k.c1p  = pk(0.0081f, 0.0081f);   // 81*C1
    k.c2p  = pk(0.0729f, 0.0729f);   // 81*C2
    k.nhp  = pk(-0.5f, -0.5f);
    k.php  = pk(0.5f, 0.5f);

    u64 acc0 = pk(0.0f, 0.0f), acc1 = pk(0.0f, 0.0f);
    if (blockIdx.x == 0 || blockIdx.x == BLOCKS_X - 1) {
        process<true >(xp, yp, r0, base, hcol, doHalo, lane, wseg, k, acc0, acc1);
    } else {
        process<false>(xp, yp, r0, base, hcol, doHalo, lane, wseg, k, acc0, acc1);
    }

    // ---- block reduction ----
    u64 acc = add2(acc0, acc1);
    float alo, ahi; unpk(acc, alo, ahi);
    float accf = alo + ahi;
    #pragma unroll
    for (int o = 16; o > 0; o >>= 1)
        accf += __shfl_xor_sync(0xffffffffu, accf, o);

    __shared__ float wsum[4];
    __shared__ int   last_flag;
    if (lane == 0) wsum[wseg] = accf;
    __syncthreads();

    if (tid == 0) {
        float p = wsum[0] + wsum[1] + wsum[2] + wsum[3];
        g_partials[blockIdx.y * gridDim.x + blockIdx.x] = p;
        __threadfence();
        unsigned t = atomicAdd(&g_count, 1u);
        last_flag = (t == NBLOCKS - 1);
    }
    __syncthreads();

    if (last_flag) {
        double s = 0.0;
        for (int i = tid; i < NBLOCKS; i += 128)
            s += (double)__ldcg(&g_partials[i]);
        #pragma unroll
        for (int o = 16; o > 0; o >>= 1)
            s += __shfl_xor_sync(0xffffffffu, s, o);
        __shared__ double dsum[4];
        if (lane == 0) dsum[wseg] = s;
        __syncthreads();
        if (tid == 0) {
            double total = dsum[0] + dsum[1] + dsum[2] + dsum[3];
            out[0] = (float)(total / (double)((size_t)PLANES * H * W));
            g_count = 0;  // reset for next graph replay
        }
    }
}

extern "C" void kernel_launch(void* const* d_in, const int* in_sizes, int n_in,
                              void* d_out, int out_size) {
    const float* x = (const float*)d_in[0];
    const float* y = (const float*)d_in[1];
    float* out = (float*)d_out;

    dim3 grid(BLOCKS_X, PLANES);
    ssim_main<<<grid, 128>>>(x, y, out);
}

// round 10
// speedup vs baseline: 2.2149x; 2.2149x over previous
#include <cuda_runtime.h>
#include <cstdint>

// SSIM loss, NCHW (32,3,512,512) fp32, 3x3 box, reflect pad 1, scalar mean.
// R9: R5 math/structure (best known, 59.9us) with the 32-row loop ROLLED
// (#pragma unroll 1) so the hot loop fits in L1.5 I$ (~10KB vs ~72KB fully
// unrolled). Branch-free upper reflect via min(i, 2(H-1)-i); lower reflect
// only in the prologue. __launch_bounds__(128,6) guards register pressure.

#define H 512
#define W 512
#define PLANES (32 * 3)
#define RPB 32
#define BLOCKS_X (H / RPB)           // 16
#define NBLOCKS (BLOCKS_X * PLANES)  // 1536

typedef unsigned long long u64;

__device__ float g_partials[NBLOCKS];
__device__ unsigned int g_count = 0;

__device__ __forceinline__ u64 pk(float lo, float hi) {
    u64 r; asm("mov.b64 %0, {%1, %2};" : "=l"(r) : "f"(lo), "f"(hi)); return r;
}
__device__ __forceinline__ void unpk(u64 v, float& lo, float& hi) {
    asm("mov.b64 {%0, %1}, %2;" : "=f"(lo), "=f"(hi) : "l"(v));
}
__device__ __forceinline__ u64 add2(u64 a, u64 b) {
    u64 d; asm("add.rn.f32x2 %0, %1, %2;" : "=l"(d) : "l"(a), "l"(b)); return d;
}
__device__ __forceinline__ u64 sub2(u64 a, u64 b) {
    u64 d; asm("sub.rn.f32x2 %0, %1, %2;" : "=l"(d) : "l"(a), "l"(b)); return d;
}
__device__ __forceinline__ u64 mul2(u64 a, u64 b) {
    u64 d; asm("mul.rn.f32x2 %0, %1, %2;" : "=l"(d) : "l"(a), "l"(b)); return d;
}
__device__ __forceinline__ u64 fma2(u64 a, u64 b, u64 c) {
    u64 d; asm("fma.rn.f32x2 %0, %1, %2, %3;" : "=l"(d) : "l"(a), "l"(b), "l"(c)); return d;
}
__device__ __forceinline__ float rcpf(float x) {
    float r; asm("rcp.approx.ftz.f32 %0, %1;" : "=f"(r) : "f"(x)); return r;
}

// Branch-free reflect for the in-loop range i in [2, 2H-2]:
// for i <= H-1, 2(H-1)-i >= i so min() returns i; above, returns 2(H-1)-i.
__device__ __forceinline__ int refl_hi(int i) {
    return min(i, 2 * (H - 1) - i);
}

// Raw row: packed x,y for 4 columns + halo scalars (lanes 0/31 only).
struct RowR { u64 X0, X1, Y0, Y1; float hX, hY; };

struct K { u64 twop, n2p, p18, p9, c1p, c2p, nhp, php; };

__device__ __forceinline__ void load_row(RowR& R,
                                         const float* __restrict__ xp,
                                         const float* __restrict__ yp,
                                         int rr, int base, int hcol, bool doHalo) {
    const float4 xv = *reinterpret_cast<const float4*>(xp + rr * W + base);
    const float4 yv = *reinterpret_cast<const float4*>(yp + rr * W + base);
    R.X0 = pk(xv.x, xv.y); R.X1 = pk(xv.z, xv.w);
    R.Y0 = pk(yv.x, yv.y); R.Y1 = pk(yv.z, yv.w);
    if (doHalo) {
        R.hX = __ldg(xp + rr * W + hcol);
        R.hY = __ldg(yp + rr * W + hcol);
    }
}

// SSIM on raw 3x3 window sums (packed pixel pair); /9 factors cancel:
//   n/d = (2A+81C1)(18 Sxy - 2A + 81C2) / ((B+C+81C1)(9(Sxx+Syy)-B-C+81C2))
__device__ __forceinline__ u64 ssim2(u64 Sx, u64 Sy, u64 Sxx, u64 Syy, u64 Sxy,
                                     const K& k) {
    u64 A  = mul2(Sx, Sy);
    u64 B  = mul2(Sx, Sx);
    u64 C  = mul2(Sy, Sy);
    u64 n1 = fma2(A, k.twop, k.c1p);
    u64 t  = fma2(A, k.n2p,  k.c2p);
    u64 n2 = fma2(Sxy, k.p18, t);
    u64 n  = mul2(n1, n2);
    u64 BC = add2(B, C);
    u64 d1 = add2(BC, k.c1p);
    u64 u  = sub2(k.c2p, BC);
    u64 d2 = fma2(add2(Sxx, Syy), k.p9, u);
    u64 d  = mul2(d1, d2);
    float dd0, dd1; unpk(d, dd0, dd1);
    u64 rp = pk(rcpf(dd0), rcpf(dd1));
    u64 q  = mul2(n, rp);
    return fma2(q, k.nhp, k.php);
}

// Horizontal packed 3-sum of vertical sums v0 (px 0,1), v1 (px 2,3), halo hv.
#define HQ(q)                                                                 \
    float a0_##q, a1_##q, a2_##q, a3_##q;                                     \
    unpk(v0_##q, a0_##q, a1_##q);                                             \
    unpk(v1_##q, a2_##q, a3_##q);                                             \
    float lv_##q = __shfl_up_sync(0xffffffffu, a3_##q, 1);                    \
    float rv_##q = __shfl_down_sync(0xffffffffu, a0_##q, 1);                  \
    if (lane == 0)  lv_##q = (wseg == 0) ? a1_##q : hv_##q;                   \
    if (lane == 31) rv_##q = (wseg == 3) ? a2_##q : hv_##q;                   \
    u64 mid_##q = pk(a1_##q, a2_##q);                                         \
    u64 h0_##q = add2(add2(pk(lv_##q, a0_##q), v0_##q), mid_##q);             \
    u64 h1_##q = add2(add2(mid_##q, v1_##q), pk(a3_##q, rv_##q));

__device__ __forceinline__ void emit(const RowR& A, const RowR& B, const RowR& C,
                                     u64& acc, int lane, int wseg, const K& k) {
    // vertical 3-sums; squares/products as FMA chains
    u64 v0_X  = add2(add2(A.X0, B.X0), C.X0);
    u64 v1_X  = add2(add2(A.X1, B.X1), C.X1);
    u64 v0_Y  = add2(add2(A.Y0, B.Y0), C.Y0);
    u64 v1_Y  = add2(add2(A.Y1, B.Y1), C.Y1);
    u64 v0_XX = fma2(A.X0, A.X0, fma2(B.X0, B.X0, mul2(C.X0, C.X0)));
    u64 v1_XX = fma2(A.X1, A.X1, fma2(B.X1, B.X1, mul2(C.X1, C.X1)));
    u64 v0_YY = fma2(A.Y0, A.Y0, fma2(B.Y0, B.Y0, mul2(C.Y0, C.Y0)));
    u64 v1_YY = fma2(A.Y1, A.Y1, fma2(B.Y1, B.Y1, mul2(C.Y1, C.Y1)));
    u64 v0_XY = fma2(A.X0, A.Y0, fma2(B.X0, B.Y0, mul2(C.X0, C.Y0)));
    u64 v1_XY = fma2(A.X1, A.Y1, fma2(B.X1, B.Y1, mul2(C.X1, C.Y1)));

    // halo vertical sums (meaningful on lanes 0/31 only)
    float hv_X  = A.hX + B.hX + C.hX;
    float hv_Y  = A.hY + B.hY + C.hY;
    float hv_XX = fmaf(A.hX, A.hX, fmaf(B.hX, B.hX, C.hX * C.hX));
    float hv_YY = fmaf(A.hY, A.hY, fmaf(B.hY, B.hY, C.hY * C.hY));
    float hv_XY = fmaf(A.hX, A.hY, fmaf(B.hX, B.hY, C.hX * C.hY));

    HQ(X) HQ(Y) HQ(XX) HQ(YY) HQ(XY)
    acc = add2(acc, ssim2(h0_X, h0_Y, h0_XX, h0_YY, h0_XY, k));
    acc = add2(acc, ssim2(h1_X, h1_Y, h1_XX, h1_YY, h1_XY, k));
}

__global__ __launch_bounds__(128, 6)
void ssim_main(const float* __restrict__ x, const float* __restrict__ y,
               float* __restrict__ out) {
    const int tid   = threadIdx.x;
    const int lane  = tid & 31;
    const int wseg  = tid >> 5;                 // 0..3, 128-col segment
    const int plane = blockIdx.y;
    const int r0    = blockIdx.x * RPB;

    const int segbase = wseg * 128;
    const int base    = segbase + lane * 4;
    const float* __restrict__ xp = x + (size_t)plane * H * W;
    const float* __restrict__ yp = y + (size_t)plane * H * W;

    const int  hcol   = (lane == 0) ? ((wseg == 0) ? 1 : segbase - 1)
                                    : ((wseg == 3) ? 510 : segbase + 128);
    const bool doHalo = (lane == 0) || (lane == 31);

    K k;
    k.twop = pk(2.0f, 2.0f);
    k.n2p  = pk(-2.0f, -2.0f);
    k.p18  = pk(18.0f, 18.0f);
    k.p9   = pk(9.0f, 9.0f);
    k.c1p  = pk(0.0081f, 0.0081f);   // 81*C1
    k.c2p  = pk(0.0729f, 0.0729f);   // 81*C2
    k.nhp  = pk(-0.5f, -0.5f);
    k.php  = pk(0.5f, 0.5f);

    // ---- pipelined 4-buffer ring: load row r+2 before emitting row r ----
    RowR b0, b1, b2, b3;
    load_row(b0, xp, yp, (r0 == 0) ? 1 : (r0 - 1), base, hcol, doHalo);
    load_row(b1, xp, yp, r0,     base, hcol, doHalo);
    load_row(b2, xp, yp, r0 + 1, base, hcol, doHalo);

    u64 acc0 = pk(0.0f, 0.0f), acc1 = pk(0.0f, 0.0f);
    // ROLLED loop: hot body ~4 emits = ~10KB, fits L1.5 I$ (vs ~72KB unrolled)
    #pragma unroll 1
    for (int j = 0; j < RPB; j += 4) {
        const int rr = r0 + j;
        load_row(b3, xp, yp, refl_hi(rr + 2), base, hcol, doHalo);
        emit(b0, b1, b2, acc0, lane, wseg, k);                 // row rr
        load_row(b0, xp, yp, refl_hi(rr + 3), base, hcol, doHalo);
        emit(b1, b2, b3, acc1, lane, wseg, k);                 // row rr+1
        load_row(b1, xp, yp, refl_hi(rr + 4), base, hcol, doHalo);
        emit(b2, b3, b0, acc0, lane, wseg, k);                 // row rr+2
        load_row(b2, xp, yp, refl_hi(rr + 5), base, hcol, doHalo);
        emit(b3, b0, b1, acc1, lane, wseg, k);                 // row rr+3
    }

    // ---- block reduction ----
    u64 acc = add2(acc0, acc1);
    float alo, ahi; unpk(acc, alo, ahi);
    float accf = alo + ahi;
    #pragma unroll
    for (int o = 16; o > 0; o >>= 1)
        accf += __shfl_xor_sync(0xffffffffu, accf, o);

    __shared__ float wsum[4];
    __shared__ int   last_flag;
    if (lane == 0) wsum[wseg] = accf;
    __syncthreads();

    if (tid == 0) {
        float p = wsum[0] + wsum[1] + wsum[2] + wsum[3];
        g_partials[blockIdx.y * gridDim.x + blockIdx.x] = p;
        __threadfence();
        unsigned t = atomicAdd(&g_count, 1u);
        last_flag = (t == NBLOCKS - 1);
    }
    __syncthreads();

    if (last_flag) {
        double s = 0.0;
        for (int i = tid; i < NBLOCKS; i += 128)
            s += (double)__ldcg(&g_partials[i]);
        #pragma unroll
        for (int o = 16; o > 0; o >>= 1)
            s += __shfl_xor_sync(0xffffffffu, s, o);
        __shared__ double dsum[4];
        if (lane == 0) dsum[wseg] = s;
        __syncthreads();
        if (tid == 0) {
            double total = dsum[0] + dsum[1] + dsum[2] + dsum[3];
            out[0] = (float)(total / (double)((size_t)PLANES * H * W));
            g_count = 0;  // reset for next graph replay
        }
    }
}

extern "C" void kernel_launch(void* const* d_in, const int* in_sizes, int n_in,
                              void* d_out, int out_size) {
    const float* x = (const float*)d_in[0];
    const float* y = (const float*)d_in[1];
    float* out = (float*)d_out;

    dim3 grid(BLOCKS_X, PLANES);
    ssim_main<<<grid, 128>>>(x, y, out);
}